// round 8
// baseline (speedup 1.0000x reference)
#include <cuda_runtime.h>
#include <cuda_bf16.h>
#include <math.h>
#include <stdint.h>

#define D_MODEL 1024
#define NHEADS  16
#define HDIM    64
#define BATCH   2
#define SEQ     2048
#define MTOT    (BATCH * SEQ)   // 4096

// ---------------------------------------------------------------------------
// Scratch (__device__ globals per allocation-free rule)
// ---------------------------------------------------------------------------
__device__ float g_q[(size_t)MTOT * D_MODEL];
__device__ float g_k[(size_t)MTOT * D_MODEL];
__device__ float g_v[(size_t)MTOT * D_MODEL];
__device__ float g_attn[(size_t)MTOT * D_MODEL];

__device__ __nv_bfloat16 g_xh[(size_t)MTOT * D_MODEL];
__device__ __nv_bfloat16 g_xl[(size_t)MTOT * D_MODEL];
__device__ __nv_bfloat16 g_ah[(size_t)MTOT * D_MODEL];
__device__ __nv_bfloat16 g_al[(size_t)MTOT * D_MODEL];
__device__ __nv_bfloat16 g_wh[4][(size_t)D_MODEL * D_MODEL];
__device__ __nv_bfloat16 g_wl[4][(size_t)D_MODEL * D_MODEL];

// ---------------------------------------------------------------------------
// helpers (base-target PTX only: ldmatrix / mma.sync / cp.async)
// ---------------------------------------------------------------------------
__device__ __forceinline__ uint32_t smem_u32(const void* p) {
    uint32_t a;
    asm("{ .reg .u64 t; cvta.to.shared.u64 t, %1; cvt.u32.u64 %0, t; }"
        : "=r"(a) : "l"(p));
    return a;
}

__device__ __forceinline__ void ldsm4(uint32_t* r, uint32_t addr) {
    asm volatile("ldmatrix.sync.aligned.m8n8.x4.shared.b16 {%0,%1,%2,%3}, [%4];"
                 : "=r"(r[0]), "=r"(r[1]), "=r"(r[2]), "=r"(r[3]) : "r"(addr));
}

__device__ __forceinline__ void mma16816(float* d, const uint32_t* a,
                                         uint32_t b0, uint32_t b1) {
    asm volatile(
        "mma.sync.aligned.m16n8k16.row.col.f32.bf16.bf16.f32 "
        "{%0,%1,%2,%3}, {%4,%5,%6,%7}, {%8,%9}, {%0,%1,%2,%3};"
        : "+f"(d[0]), "+f"(d[1]), "+f"(d[2]), "+f"(d[3])
        : "r"(a[0]), "r"(a[1]), "r"(a[2]), "r"(a[3]), "r"(b0), "r"(b1));
}

__device__ __forceinline__ void cp16(uint32_t saddr, const void* gaddr) {
    asm volatile("cp.async.cg.shared.global [%0], [%1], 16;"
                 :: "r"(saddr), "l"(gaddr));
}
#define CP_COMMIT() asm volatile("cp.async.commit_group;" ::: "memory")
#define CP_WAIT0()  asm volatile("cp.async.wait_group 0;" ::: "memory")

// ---------------------------------------------------------------------------
// fp32 -> (bf16 hi, bf16 lo) split, vectorized x4
// ---------------------------------------------------------------------------
__global__ void split_bf16(const float4* __restrict__ in,
                           __nv_bfloat162* __restrict__ hi,
                           __nv_bfloat162* __restrict__ lo, int n4) {
    int i = blockIdx.x * blockDim.x + threadIdx.x;
    if (i >= n4) return;
    float4 x = in[i];
    __nv_bfloat16 h0 = __float2bfloat16(x.x);
    __nv_bfloat16 h1 = __float2bfloat16(x.y);
    __nv_bfloat16 h2 = __float2bfloat16(x.z);
    __nv_bfloat16 h3 = __float2bfloat16(x.w);
    __nv_bfloat16 l0 = __float2bfloat16(x.x - __bfloat162float(h0));
    __nv_bfloat16 l1 = __float2bfloat16(x.y - __bfloat162float(h1));
    __nv_bfloat16 l2 = __float2bfloat16(x.z - __bfloat162float(h2));
    __nv_bfloat16 l3 = __float2bfloat16(x.w - __bfloat162float(h3));
    hi[i * 2 + 0] = __halves2bfloat162(h0, h1);
    hi[i * 2 + 1] = __halves2bfloat162(h2, h3);
    lo[i * 2 + 0] = __halves2bfloat162(l0, l1);
    lo[i * 2 + 1] = __halves2bfloat162(l2, l3);
}

// ---------------------------------------------------------------------------
// C[M,N] = (Ah+Al)[M,K] @ (Bh+Bl)[N,K]^T via HMMA (drop Al*Bl).
// 128x128 CTA tile, BK=64, 256 threads (8 warps, 64x32 warp tiles),
// double-buffered cp.async, fp32 register accumulators.
// ---------------------------------------------------------------------------
#define BK    64
#define RSB   144                      // smem row stride bytes (128B data + 16B pad)
#define TILEB (128 * RSB)              // 18432 B per tile
#define GSMEM (2 * 4 * TILEB)          // 147456 B (2 buffers x Ah/Al/Bh/Bl)

__global__ __launch_bounds__(256) void gemm_hmma(
    const __nv_bfloat16* __restrict__ Ah, const __nv_bfloat16* __restrict__ Al,
    const __nv_bfloat16* __restrict__ Bh, const __nv_bfloat16* __restrict__ Bl,
    float* __restrict__ C, int M, int N, int K) {
    extern __shared__ char smraw[];
    const uint32_t sbase = smem_u32(smraw);

    const int tid  = threadIdx.x;
    const int lane = tid & 31;
    const int wid  = tid >> 5;
    const int wm   = wid & 1;    // 0..1 -> m half (64)
    const int wn   = wid >> 1;   // 0..3 -> n quarter (32)
    const int m0   = blockIdx.y * 128;
    const int n0   = blockIdx.x * 128;

    float acc[4][4][4];
#pragma unroll
    for (int mi = 0; mi < 4; mi++)
#pragma unroll
        for (int ni = 0; ni < 4; ni++)
#pragma unroll
            for (int r = 0; r < 4; r++) acc[mi][ni][r] = 0.f;

    // per-thread loader mapping: vector u = tid*4+j ; row=u>>3, col16=u&7
    const int NCH = K / BK;   // 16

    auto issue_chunk = [&](int ch, int buf) {
        const uint32_t sb = sbase + (uint32_t)buf * 4 * TILEB;
        const int k0 = ch * BK;
#pragma unroll
        for (int j = 0; j < 4; j++) {
            int u = tid * 4 + j;
            int r = u >> 3, c = u & 7;
            uint32_t so = (uint32_t)(r * RSB + c * 16);
            size_t gA = (size_t)(m0 + r) * K + k0 + c * 8;
            size_t gB = (size_t)(n0 + r) * K + k0 + c * 8;
            cp16(sb + 0 * TILEB + so, Ah + gA);
            cp16(sb + 1 * TILEB + so, Al + gA);
            cp16(sb + 2 * TILEB + so, Bh + gB);
            cp16(sb + 3 * TILEB + so, Bl + gB);
        }
        CP_COMMIT();
    };

    issue_chunk(0, 0);

    // ldmatrix address bases (row/k lane mapping per fragment conventions)
    const uint32_t aRowOff = (uint32_t)((wm * 64 + (lane & 15)) * RSB + (lane >> 4) * 16);
    const uint32_t bRowOff = (uint32_t)((wn * 32 + (lane & 7) + ((lane >> 4) << 3)) * RSB
                                        + ((lane >> 3) & 1) * 16);

    for (int ch = 0; ch < NCH; ch++) {
        CP_WAIT0();
        __syncthreads();
        if (ch + 1 < NCH) issue_chunk(ch + 1, (ch + 1) & 1);

        const uint32_t sb = sbase + (uint32_t)(ch & 1) * 4 * TILEB;
        const uint32_t aBase = sb + aRowOff;
        const uint32_t bBase = sb + 2 * TILEB + bRowOff;

#pragma unroll
        for (int ks = 0; ks < 4; ks++) {            // K=16 per step
            const uint32_t koff = (uint32_t)(ks * 32);   // bytes
            uint32_t ah[4][4], al[4][4];
#pragma unroll
            for (int mi = 0; mi < 4; mi++) {
                ldsm4(ah[mi], aBase + (uint32_t)(mi * 16 * RSB) + koff);
                ldsm4(al[mi], aBase + TILEB + (uint32_t)(mi * 16 * RSB) + koff);
            }
            uint32_t bh[2][4], bl[2][4];
#pragma unroll
            for (int n2 = 0; n2 < 2; n2++) {
                ldsm4(bh[n2], bBase + (uint32_t)(n2 * 16 * RSB) + koff);
                ldsm4(bl[n2], bBase + TILEB + (uint32_t)(n2 * 16 * RSB) + koff);
            }
#pragma unroll
            for (int mi = 0; mi < 4; mi++)
#pragma unroll
                for (int ni = 0; ni < 4; ni++) {
                    uint32_t h0 = bh[ni >> 1][(ni & 1) * 2];
                    uint32_t h1 = bh[ni >> 1][(ni & 1) * 2 + 1];
                    uint32_t q0 = bl[ni >> 1][(ni & 1) * 2];
                    uint32_t q1 = bl[ni >> 1][(ni & 1) * 2 + 1];
                    mma16816(acc[mi][ni], ah[mi], h0, h1);
                    mma16816(acc[mi][ni], ah[mi], q0, q1);
                    mma16816(acc[mi][ni], al[mi], h0, h1);
                }
        }
        __syncthreads();
    }

    // epilogue: D fragment (row=lane/4 & +8, col=2*(lane%4))
#pragma unroll
    for (int mi = 0; mi < 4; mi++) {
        int gr = m0 + wm * 64 + mi * 16 + (lane >> 2);
        int gc = n0 + wn * 32 + (lane & 3) * 2;
        float* C0 = C + (size_t)gr * N + gc;
        float* C1 = C + (size_t)(gr + 8) * N + gc;
#pragma unroll
        for (int ni = 0; ni < 4; ni++) {
            *(float2*)(C0 + ni * 8) = make_float2(acc[mi][ni][0], acc[mi][ni][1]);
            *(float2*)(C1 + ni * 8) = make_float2(acc[mi][ni][2], acc[mi][ni][3]);
        }
    }
}

// ---------------------------------------------------------------------------
// Flash attention (causal), fp32 — unchanged from round-2 baseline.
// ---------------------------------------------------------------------------
#define LDP 65

__global__ __launch_bounds__(128) void flash_attn(const float* __restrict__ Q,
                                                  const float* __restrict__ Kg,
                                                  const float* __restrict__ V,
                                                  float* __restrict__ O) {
    extern __shared__ float smf[];
    float* Qs = smf;
    float* Ks = Qs + 64 * LDP;
    float* Vs = Ks + 64 * LDP;
    float* Ps = Vs + 64 * LDP;

    const int qt = blockIdx.x;
    const int bh = blockIdx.y;
    const int b  = bh >> 4;
    const int h  = bh & 15;
    const int q0 = qt * 64;
    const size_t bbase = ((size_t)b * SEQ) * D_MODEL + (size_t)h * HDIM;

    const int tid = threadIdx.x;

    for (int i = tid; i < 64 * 16; i += 128) {
        int r = i >> 4, c = (i & 15) * 4;
        float4 t = *(const float4*)(Q + bbase + (size_t)(q0 + r) * D_MODEL + c);
        Qs[r * LDP + c + 0] = t.x; Qs[r * LDP + c + 1] = t.y;
        Qs[r * LDP + c + 2] = t.z; Qs[r * LDP + c + 3] = t.w;
    }

    const int lane = tid & 31;
    const int warp = tid >> 5;
    const int grp  = lane >> 2;
    const int r0   = (warp * 8 + grp) * 2;
    const int r1   = r0 + 1;
    const int kq   = lane & 3;

    float m0 = -INFINITY, m1 = -INFINITY;
    float l0 = 0.f, l1 = 0.f;
    float o0[16], o1[16];
#pragma unroll
    for (int i = 0; i < 16; i++) { o0[i] = 0.f; o1[i] = 0.f; }

    for (int t = 0; t <= qt; t++) {
        const int n0 = t * 64;
        __syncthreads();
        for (int i = tid; i < 64 * 16; i += 128) {
            int r = i >> 4, c = (i & 15) * 4;
            size_t gi = bbase + (size_t)(n0 + r) * D_MODEL + c;
            float4 kt = *(const float4*)(Kg + gi);
            Ks[r * LDP + c + 0] = kt.x; Ks[r * LDP + c + 1] = kt.y;
            Ks[r * LDP + c + 2] = kt.z; Ks[r * LDP + c + 3] = kt.w;
            float4 vt = *(const float4*)(V + gi);
            Vs[r * LDP + c + 0] = vt.x; Vs[r * LDP + c + 1] = vt.y;
            Vs[r * LDP + c + 2] = vt.z; Vs[r * LDP + c + 3] = vt.w;
        }
        __syncthreads();

        float s0[16], s1[16];
#pragma unroll
        for (int j = 0; j < 16; j++) { s0[j] = 0.f; s1[j] = 0.f; }
#pragma unroll 4
        for (int d = 0; d < 64; d++) {
            float qa = Qs[r0 * LDP + d];
            float qb = Qs[r1 * LDP + d];
#pragma unroll
            for (int j = 0; j < 16; j++) {
                float kv = Ks[(kq * 16 + j) * LDP + d];
                s0[j] += qa * kv;
                s1[j] += qb * kv;
            }
        }

        const bool diag = (t == qt);
#pragma unroll
        for (int j = 0; j < 16; j++) {
            int kl = kq * 16 + j;
            s0[j] *= 0.125f;
            s1[j] *= 0.125f;
            if (diag) {
                if (kl > r0) s0[j] = -INFINITY;
                if (kl > r1) s1[j] = -INFINITY;
            }
        }

        float tm0 = s0[0], tm1 = s1[0];
#pragma unroll
        for (int j = 1; j < 16; j++) { tm0 = fmaxf(tm0, s0[j]); tm1 = fmaxf(tm1, s1[j]); }
        tm0 = fmaxf(tm0, __shfl_xor_sync(0xffffffffu, tm0, 1));
        tm0 = fmaxf(tm0, __shfl_xor_sync(0xffffffffu, tm0, 2));
        tm1 = fmaxf(tm1, __shfl_xor_sync(0xffffffffu, tm1, 1));
        tm1 = fmaxf(tm1, __shfl_xor_sync(0xffffffffu, tm1, 2));

        float nm0 = fmaxf(m0, tm0), nm1 = fmaxf(m1, tm1);
        float a0 = __expf(m0 - nm0);
        float a1 = __expf(m1 - nm1);

        float sum0 = 0.f, sum1 = 0.f;
#pragma unroll
        for (int j = 0; j < 16; j++) {
            float p0 = __expf(s0[j] - nm0);
            float p1 = __expf(s1[j] - nm1);
            s0[j] = p0; s1[j] = p1;
            sum0 += p0; sum1 += p1;
        }
        sum0 += __shfl_xor_sync(0xffffffffu, sum0, 1);
        sum0 += __shfl_xor_sync(0xffffffffu, sum0, 2);
        sum1 += __shfl_xor_sync(0xffffffffu, sum1, 1);
        sum1 += __shfl_xor_sync(0xffffffffu, sum1, 2);

        l0 = l0 * a0 + sum0;
        l1 = l1 * a1 + sum1;
        m0 = nm0; m1 = nm1;
#pragma unroll
        for (int i = 0; i < 16; i++) { o0[i] *= a0; o1[i] *= a1; }

#pragma unroll
        for (int j = 0; j < 16; j++) {
            Ps[r0 * LDP + kq * 16 + j] = s0[j];
            Ps[r1 * LDP + kq * 16 + j] = s1[j];
        }
        __syncthreads();

#pragma unroll 4
        for (int kk = 0; kk < 64; kk++) {
            float p0 = Ps[r0 * LDP + kk];
            float p1 = Ps[r1 * LDP + kk];
#pragma unroll
            for (int dd = 0; dd < 16; dd++) {
                float vv = Vs[kk * LDP + kq + dd * 4];
                o0[dd] += p0 * vv;
                o1[dd] += p1 * vv;
            }
        }
    }

    const float il0 = 1.f / l0, il1 = 1.f / l1;
    float* Op0 = O + bbase + (size_t)(q0 + r0) * D_MODEL;
    float* Op1 = O + bbase + (size_t)(q0 + r1) * D_MODEL;
#pragma unroll
    for (int dd = 0; dd < 16; dd++) {
        Op0[kq + dd * 4] = o0[dd] * il0;
        Op1[kq + dd * 4] = o1[dd] * il1;
    }
}

// ---------------------------------------------------------------------------
extern "C" void kernel_launch(void* const* d_in, const int* in_sizes, int n_in,
                              void* d_out, int out_size) {
    const float* x  = (const float*)d_in[0];
    const float* W[4] = { (const float*)d_in[1], (const float*)d_in[2],
                          (const float*)d_in[3], (const float*)d_in[4] };
    float* out = (float*)d_out;

    float *q, *k, *v, *attn;
    cudaGetSymbolAddress((void**)&q, g_q);
    cudaGetSymbolAddress((void**)&k, g_k);
    cudaGetSymbolAddress((void**)&v, g_v);
    cudaGetSymbolAddress((void**)&attn, g_attn);

    __nv_bfloat16 *xh, *xl, *ah, *al, *wh, *wl;
    cudaGetSymbolAddress((void**)&xh, g_xh);
    cudaGetSymbolAddress((void**)&xl, g_xl);
    cudaGetSymbolAddress((void**)&ah, g_ah);
    cudaGetSymbolAddress((void**)&al, g_al);
    cudaGetSymbolAddress((void**)&wh, g_wh);
    cudaGetSymbolAddress((void**)&wl, g_wl);

    const int NX4 = MTOT * D_MODEL / 4;      // 1048576
    const int NW4 = D_MODEL * D_MODEL / 4;   // 262144

    split_bf16<<<(NX4 + 255) / 256, 256>>>((const float4*)x,
        (__nv_bfloat162*)xh, (__nv_bfloat162*)xl, NX4);
    for (int i = 0; i < 4; i++) {
        split_bf16<<<(NW4 + 255) / 256, 256>>>((const float4*)W[i],
            (__nv_bfloat162*)(wh + (size_t)i * D_MODEL * D_MODEL),
            (__nv_bfloat162*)(wl + (size_t)i * D_MODEL * D_MODEL), NW4);
    }

    cudaFuncSetAttribute(gemm_hmma, cudaFuncAttributeMaxDynamicSharedMemorySize, GSMEM);
    dim3 gridP(D_MODEL / 128, MTOT / 128);   // (8, 32)

    gemm_hmma<<<gridP, 256, GSMEM>>>(xh, xl,
        wh + 0 * (size_t)D_MODEL * D_MODEL, wl + 0 * (size_t)D_MODEL * D_MODEL,
        q, MTOT, D_MODEL, D_MODEL);
    gemm_hmma<<<gridP, 256, GSMEM>>>(xh, xl,
        wh + 1 * (size_t)D_MODEL * D_MODEL, wl + 1 * (size_t)D_MODEL * D_MODEL,
        k, MTOT, D_MODEL, D_MODEL);
    gemm_hmma<<<gridP, 256, GSMEM>>>(xh, xl,
        wh + 2 * (size_t)D_MODEL * D_MODEL, wl + 2 * (size_t)D_MODEL * D_MODEL,
        v, MTOT, D_MODEL, D_MODEL);

    const int fa_smem = 4 * 64 * LDP * (int)sizeof(float);
    cudaFuncSetAttribute(flash_attn, cudaFuncAttributeMaxDynamicSharedMemorySize, fa_smem);
    flash_attn<<<dim3(SEQ / 64, BATCH * NHEADS), 128, fa_smem>>>(q, k, v, attn);

    split_bf16<<<(NX4 + 255) / 256, 256>>>((const float4*)attn,
        (__nv_bfloat162*)ah, (__nv_bfloat162*)al, NX4);

    gemm_hmma<<<gridP, 256, GSMEM>>>(ah, al,
        wh + 3 * (size_t)D_MODEL * D_MODEL, wl + 3 * (size_t)D_MODEL * D_MODEL,
        out, MTOT, D_MODEL, D_MODEL);
}

// round 9
// speedup vs baseline: 2.3835x; 2.3835x over previous
#include <cuda_runtime.h>
#include <cuda_bf16.h>
#include <math.h>
#include <stdint.h>

#define D_MODEL 1024
#define NHEADS  16
#define HDIM    64
#define BATCH   2
#define SEQ     2048
#define MTOT    (BATCH * SEQ)   // 4096

// ---------------------------------------------------------------------------
// Scratch (__device__ globals per allocation-free rule) — all bf16
// ---------------------------------------------------------------------------
__device__ __nv_bfloat16 g_xh[(size_t)MTOT * D_MODEL];
__device__ __nv_bfloat16 g_xl[(size_t)MTOT * D_MODEL];
__device__ __nv_bfloat16 g_wh[4][(size_t)D_MODEL * D_MODEL];
__device__ __nv_bfloat16 g_wl[4][(size_t)D_MODEL * D_MODEL];
__device__ __nv_bfloat16 g_qh[(size_t)MTOT * D_MODEL];
__device__ __nv_bfloat16 g_ql[(size_t)MTOT * D_MODEL];
__device__ __nv_bfloat16 g_kh[(size_t)MTOT * D_MODEL];
__device__ __nv_bfloat16 g_kl[(size_t)MTOT * D_MODEL];
__device__ __nv_bfloat16 g_vh[(size_t)MTOT * D_MODEL];
__device__ __nv_bfloat16 g_vl[(size_t)MTOT * D_MODEL];
__device__ __nv_bfloat16 g_vth[(size_t)MTOT * D_MODEL];  // [b,h,d,t]
__device__ __nv_bfloat16 g_vtl[(size_t)MTOT * D_MODEL];
__device__ __nv_bfloat16 g_ah[(size_t)MTOT * D_MODEL];
__device__ __nv_bfloat16 g_al[(size_t)MTOT * D_MODEL];

// ---------------------------------------------------------------------------
// helpers (base-target PTX only: ldmatrix / mma.sync / cp.async)
// ---------------------------------------------------------------------------
__device__ __forceinline__ uint32_t smem_u32(const void* p) {
    uint32_t a;
    asm("{ .reg .u64 t; cvta.to.shared.u64 t, %1; cvt.u32.u64 %0, t; }"
        : "=r"(a) : "l"(p));
    return a;
}

__device__ __forceinline__ void ldsm4(uint32_t* r, uint32_t addr) {
    asm volatile("ldmatrix.sync.aligned.m8n8.x4.shared.b16 {%0,%1,%2,%3}, [%4];"
                 : "=r"(r[0]), "=r"(r[1]), "=r"(r[2]), "=r"(r[3]) : "r"(addr));
}

__device__ __forceinline__ void mma16816(float* d, const uint32_t* a,
                                         uint32_t b0, uint32_t b1) {
    asm volatile(
        "mma.sync.aligned.m16n8k16.row.col.f32.bf16.bf16.f32 "
        "{%0,%1,%2,%3}, {%4,%5,%6,%7}, {%8,%9}, {%0,%1,%2,%3};"
        : "+f"(d[0]), "+f"(d[1]), "+f"(d[2]), "+f"(d[3])
        : "r"(a[0]), "r"(a[1]), "r"(a[2]), "r"(a[3]), "r"(b0), "r"(b1));
}

__device__ __forceinline__ void cp16(uint32_t saddr, const void* gaddr) {
    asm volatile("cp.async.cg.shared.global [%0], [%1], 16;"
                 :: "r"(saddr), "l"(gaddr));
}
#define CP_COMMIT() asm volatile("cp.async.commit_group;" ::: "memory")
#define CP_WAIT0()  asm volatile("cp.async.wait_group 0;" ::: "memory")
#define CP_WAIT1()  asm volatile("cp.async.wait_group 1;" ::: "memory")

// fp32 pair -> packed bf16x2 (hi) + packed bf16x2 (lo residual)
__device__ __forceinline__ void split2(float x, float y, uint32_t& hi, uint32_t& lo) {
    __nv_bfloat16 hx = __float2bfloat16(x), hy = __float2bfloat16(y);
    __nv_bfloat16 lx = __float2bfloat16(x - __bfloat162float(hx));
    __nv_bfloat16 ly = __float2bfloat16(y - __bfloat162float(hy));
    __nv_bfloat162 h2 = __halves2bfloat162(hx, hy);
    __nv_bfloat162 l2 = __halves2bfloat162(lx, ly);
    hi = *(uint32_t*)&h2;
    lo = *(uint32_t*)&l2;
}

// ---------------------------------------------------------------------------
// fp32 -> (bf16 hi, bf16 lo) split, vectorized x4
// ---------------------------------------------------------------------------
__global__ void split_bf16(const float4* __restrict__ in,
                           __nv_bfloat162* __restrict__ hi,
                           __nv_bfloat162* __restrict__ lo, int n4) {
    int i = blockIdx.x * blockDim.x + threadIdx.x;
    if (i >= n4) return;
    float4 x = in[i];
    uint32_t h0, l0, h1, l1;
    split2(x.x, x.y, h0, l0);
    split2(x.z, x.w, h1, l1);
    ((uint32_t*)hi)[i * 2 + 0] = h0;
    ((uint32_t*)hi)[i * 2 + 1] = h1;
    ((uint32_t*)lo)[i * 2 + 0] = l0;
    ((uint32_t*)lo)[i * 2 + 1] = l1;
}

// ---------------------------------------------------------------------------
// C = (Ah+Al)[M,K] @ (Bh+Bl)[N,K]^T via HMMA (drop Al*Bl).
// Optional fp32 output Cf and/or bf16 hi/lo outputs Ch/Cl.
// ---------------------------------------------------------------------------
#define BK    64
#define RSB   144
#define TILEB (128 * RSB)
#define GSMEM (2 * 4 * TILEB)

__global__ __launch_bounds__(256) void gemm_hmma(
    const __nv_bfloat16* __restrict__ Ah, const __nv_bfloat16* __restrict__ Al,
    const __nv_bfloat16* __restrict__ Bh, const __nv_bfloat16* __restrict__ Bl,
    float* __restrict__ Cf, __nv_bfloat16* __restrict__ Ch,
    __nv_bfloat16* __restrict__ Cl, int M, int N, int K) {
    extern __shared__ char smraw[];
    const uint32_t sbase = smem_u32(smraw);

    const int tid  = threadIdx.x;
    const int lane = tid & 31;
    const int wid  = tid >> 5;
    const int wm   = wid & 1;
    const int wn   = wid >> 1;
    const int m0   = blockIdx.y * 128;
    const int n0   = blockIdx.x * 128;

    float acc[4][4][4];
#pragma unroll
    for (int mi = 0; mi < 4; mi++)
#pragma unroll
        for (int ni = 0; ni < 4; ni++)
#pragma unroll
            for (int r = 0; r < 4; r++) acc[mi][ni][r] = 0.f;

    const int NCH = K / BK;

    auto issue_chunk = [&](int ch, int buf) {
        const uint32_t sb = sbase + (uint32_t)buf * 4 * TILEB;
        const int k0 = ch * BK;
#pragma unroll
        for (int j = 0; j < 4; j++) {
            int u = tid * 4 + j;
            int r = u >> 3, c = u & 7;
            uint32_t so = (uint32_t)(r * RSB + c * 16);
            size_t gA = (size_t)(m0 + r) * K + k0 + c * 8;
            size_t gB = (size_t)(n0 + r) * K + k0 + c * 8;
            cp16(sb + 0 * TILEB + so, Ah + gA);
            cp16(sb + 1 * TILEB + so, Al + gA);
            cp16(sb + 2 * TILEB + so, Bh + gB);
            cp16(sb + 3 * TILEB + so, Bl + gB);
        }
        CP_COMMIT();
    };

    issue_chunk(0, 0);

    const uint32_t aRowOff = (uint32_t)((wm * 64 + (lane & 15)) * RSB + (lane >> 4) * 16);
    const uint32_t bRowOff = (uint32_t)((wn * 32 + (lane & 7) + ((lane >> 4) << 3)) * RSB
                                        + ((lane >> 3) & 1) * 16);

    for (int ch = 0; ch < NCH; ch++) {
        CP_WAIT0();
        __syncthreads();
        if (ch + 1 < NCH) issue_chunk(ch + 1, (ch + 1) & 1);

        const uint32_t sb = sbase + (uint32_t)(ch & 1) * 4 * TILEB;
        const uint32_t aBase = sb + aRowOff;
        const uint32_t bBase = sb + 2 * TILEB + bRowOff;

#pragma unroll
        for (int ks = 0; ks < 4; ks++) {
            const uint32_t koff = (uint32_t)(ks * 32);
            uint32_t ah[4][4], al[4][4];
#pragma unroll
            for (int mi = 0; mi < 4; mi++) {
                ldsm4(ah[mi], aBase + (uint32_t)(mi * 16 * RSB) + koff);
                ldsm4(al[mi], aBase + TILEB + (uint32_t)(mi * 16 * RSB) + koff);
            }
            uint32_t bh[2][4], bl[2][4];
#pragma unroll
            for (int n2 = 0; n2 < 2; n2++) {
                ldsm4(bh[n2], bBase + (uint32_t)(n2 * 16 * RSB) + koff);
                ldsm4(bl[n2], bBase + TILEB + (uint32_t)(n2 * 16 * RSB) + koff);
            }
#pragma unroll
            for (int mi = 0; mi < 4; mi++)
#pragma unroll
                for (int ni = 0; ni < 4; ni++) {
                    uint32_t h0 = bh[ni >> 1][(ni & 1) * 2];
                    uint32_t h1 = bh[ni >> 1][(ni & 1) * 2 + 1];
                    uint32_t q0 = bl[ni >> 1][(ni & 1) * 2];
                    uint32_t q1 = bl[ni >> 1][(ni & 1) * 2 + 1];
                    mma16816(acc[mi][ni], ah[mi], h0, h1);
                    mma16816(acc[mi][ni], ah[mi], q0, q1);
                    mma16816(acc[mi][ni], al[mi], h0, h1);
                }
        }
        __syncthreads();
    }

#pragma unroll
    for (int mi = 0; mi < 4; mi++) {
        int gr = m0 + wm * 64 + mi * 16 + (lane >> 2);
        int gc = n0 + wn * 32 + (lane & 3) * 2;
        if (Cf) {
            float* C0 = Cf + (size_t)gr * N + gc;
            float* C1 = Cf + (size_t)(gr + 8) * N + gc;
#pragma unroll
            for (int ni = 0; ni < 4; ni++) {
                *(float2*)(C0 + ni * 8) = make_float2(acc[mi][ni][0], acc[mi][ni][1]);
                *(float2*)(C1 + ni * 8) = make_float2(acc[mi][ni][2], acc[mi][ni][3]);
            }
        }
        if (Ch) {
            size_t i0 = (size_t)gr * N + gc;
            size_t i1 = (size_t)(gr + 8) * N + gc;
#pragma unroll
            for (int ni = 0; ni < 4; ni++) {
                uint32_t h, l;
                split2(acc[mi][ni][0], acc[mi][ni][1], h, l);
                *(uint32_t*)(Ch + i0 + ni * 8) = h;
                *(uint32_t*)(Cl + i0 + ni * 8) = l;
                split2(acc[mi][ni][2], acc[mi][ni][3], h, l);
                *(uint32_t*)(Ch + i1 + ni * 8) = h;
                *(uint32_t*)(Cl + i1 + ni * 8) = l;
            }
        }
    }
}

// ---------------------------------------------------------------------------
// V transpose: [b,t,h*64+d] bf16 -> [b,h,d,t] bf16 (hi and lo together)
// ---------------------------------------------------------------------------
__global__ __launch_bounds__(256) void vtrans(
    const __nv_bfloat16* __restrict__ vh, const __nv_bfloat16* __restrict__ vl,
    __nv_bfloat16* __restrict__ vth, __nv_bfloat16* __restrict__ vtl) {
    __shared__ __nv_bfloat16 th[64][72];
    __shared__ __nv_bfloat16 tl[64][72];
    const int tt = blockIdx.x, bh = blockIdx.y;
    const int b = bh >> 4, h = bh & 15;
    const int tid = threadIdx.x;

#pragma unroll
    for (int jj = 0; jj < 2; jj++) {
        int u = tid + 256 * jj;          // 0..511
        int r = u >> 3, c = u & 7;
        size_t g = ((size_t)(b * SEQ + tt * 64 + r)) * D_MODEL + h * 64 + c * 8;
        *(uint4*)&th[r][c * 8] = *(const uint4*)(vh + g);
        *(uint4*)&tl[r][c * 8] = *(const uint4*)(vl + g);
    }
    __syncthreads();
#pragma unroll
    for (int jj = 0; jj < 2; jj++) {
        int u = tid + 256 * jj;
        int d = u >> 3, c = u & 7;
        __nv_bfloat16 bh8[8], bl8[8];
#pragma unroll
        for (int e = 0; e < 8; e++) { bh8[e] = th[c * 8 + e][d]; bl8[e] = tl[c * 8 + e][d]; }
        size_t g = ((size_t)(bh * 64 + d)) * SEQ + tt * 64 + c * 8;
        *(uint4*)(vth + g) = *(uint4*)bh8;
        *(uint4*)(vtl + g) = *(uint4*)bl8;
    }
}

// ---------------------------------------------------------------------------
// Tensor-core causal flash attention, bf16 hi/lo split everywhere.
// Block: 64 q-rows of one (b,h). 4 warps, each owns m16 of S/O.
// Outputs O directly as bf16 hi/lo at [b,t,h*64+d].
// ---------------------------------------------------------------------------
#define FRSB   144
#define FTILEB (64 * FRSB)                 // 9216
#define FA_SMEM (10 * FTILEB)              // Qh,Ql + 2x{Kh,Kl,Vh,Vl} = 92160

__global__ __launch_bounds__(128) void flash_hmma(
    const __nv_bfloat16* __restrict__ qh, const __nv_bfloat16* __restrict__ ql,
    const __nv_bfloat16* __restrict__ kh, const __nv_bfloat16* __restrict__ kl,
    const __nv_bfloat16* __restrict__ vth, const __nv_bfloat16* __restrict__ vtl,
    __nv_bfloat16* __restrict__ oh, __nv_bfloat16* __restrict__ ol) {
    extern __shared__ char smraw[];
    const uint32_t sb  = smem_u32(smraw);
    const uint32_t sQh = sb, sQl = sb + FTILEB;

    const int qt = blockIdx.x, bh = blockIdx.y;
    const int b = bh >> 4, h = bh & 15;
    const int q0 = qt * 64;
    const int tid = threadIdx.x, lane = tid & 31, w = tid >> 5;

    const size_t qbase = ((size_t)(b * SEQ + q0)) * D_MODEL + h * HDIM;
    const size_t kbase = ((size_t)(b * SEQ)) * D_MODEL + h * HDIM;
    const size_t vbase = ((size_t)bh * HDIM) * SEQ;

    // Q tile load (group 0)
#pragma unroll
    for (int jj = 0; jj < 4; jj++) {
        int u = tid + 128 * jj;
        int r = u >> 3, c = u & 7;
        size_t g = qbase + (size_t)r * D_MODEL + c * 8;
        uint32_t so = (uint32_t)(r * FRSB + c * 16);
        cp16(sQh + so, qh + g);
        cp16(sQl + so, ql + g);
    }
    CP_COMMIT();

    auto issue_kv = [&](int t, int buf) {
        const uint32_t sk = sb + 2 * FTILEB + (uint32_t)buf * 4 * FTILEB;
        const int kv0 = t * 64;
#pragma unroll
        for (int jj = 0; jj < 4; jj++) {
            int u = tid + 128 * jj;
            int r = u >> 3, c = u & 7;
            uint32_t so = (uint32_t)(r * FRSB + c * 16);
            size_t gk = kbase + (size_t)(kv0 + r) * D_MODEL + c * 8;
            size_t gv = vbase + (size_t)r * SEQ + kv0 + c * 8;
            cp16(sk + 0 * FTILEB + so, kh + gk);
            cp16(sk + 1 * FTILEB + so, kl + gk);
            cp16(sk + 2 * FTILEB + so, vth + gv);
            cp16(sk + 3 * FTILEB + so, vtl + gv);
        }
        CP_COMMIT();
    };

    issue_kv(0, 0);

    // load Q fragments to registers (Q smem never rewritten)
    CP_WAIT1();
    __syncthreads();
    const uint32_t qAoff = (uint32_t)((w * 16 + (lane & 15)) * FRSB + (lane >> 4) * 16);
    uint32_t qhf[4][4], qlf[4][4];
#pragma unroll
    for (int ks = 0; ks < 4; ks++) {
        ldsm4(qhf[ks], sQh + qAoff + ks * 32);
        ldsm4(qlf[ks], sQl + qAoff + ks * 32);
    }

    const uint32_t bOff = (uint32_t)(((lane & 7) + ((lane >> 4) << 3)) * FRSB
                                     + ((lane >> 3) & 1) * 16);

    float m0 = -INFINITY, m1 = -INFINITY, l0 = 0.f, l1 = 0.f;
    float o[8][4];
#pragma unroll
    for (int j = 0; j < 8; j++)
#pragma unroll
        for (int r = 0; r < 4; r++) o[j][r] = 0.f;

    const int gr0 = q0 + w * 16 + (lane >> 2);

    for (int t = 0; t <= qt; t++) {
        CP_WAIT0();
        __syncthreads();
        if (t < qt) issue_kv(t + 1, (t + 1) & 1);

        const uint32_t sk  = sb + 2 * FTILEB + (uint32_t)(t & 1) * 4 * FTILEB;
        const uint32_t skh = sk, skl = sk + FTILEB;
        const uint32_t svh = sk + 2 * FTILEB, svl = sk + 3 * FTILEB;

        // ---- S = Q K^T (3-term split) ----
        float s[8][4];
#pragma unroll
        for (int j = 0; j < 8; j++)
#pragma unroll
            for (int r = 0; r < 4; r++) s[j][r] = 0.f;

#pragma unroll
        for (int ks = 0; ks < 4; ks++) {
#pragma unroll
            for (int g = 0; g < 4; g++) {
                uint32_t kf[4], lf[4];
                ldsm4(kf, skh + bOff + (uint32_t)(g * 16 * FRSB) + ks * 32);
                ldsm4(lf, skl + bOff + (uint32_t)(g * 16 * FRSB) + ks * 32);
                mma16816(s[2 * g],     qhf[ks], kf[0], kf[1]);
                mma16816(s[2 * g],     qhf[ks], lf[0], lf[1]);
                mma16816(s[2 * g],     qlf[ks], kf[0], kf[1]);
                mma16816(s[2 * g + 1], qhf[ks], kf[2], kf[3]);
                mma16816(s[2 * g + 1], qhf[ks], lf[2], lf[3]);
                mma16816(s[2 * g + 1], qlf[ks], kf[2], kf[3]);
            }
        }

        // ---- scale + causal mask + online softmax ----
        const bool diag = (t == qt);
        const int cb = t * 64 + 2 * (lane & 3);
        float tm0 = -INFINITY, tm1 = -INFINITY;
#pragma unroll
        for (int j = 0; j < 8; j++) {
            int col = cb + 8 * j;
            s[j][0] *= 0.125f; s[j][1] *= 0.125f;
            s[j][2] *= 0.125f; s[j][3] *= 0.125f;
            if (diag) {
                if (col     > gr0)     s[j][0] = -INFINITY;
                if (col + 1 > gr0)     s[j][1] = -INFINITY;
                if (col     > gr0 + 8) s[j][2] = -INFINITY;
                if (col + 1 > gr0 + 8) s[j][3] = -INFINITY;
            }
            tm0 = fmaxf(tm0, fmaxf(s[j][0], s[j][1]));
            tm1 = fmaxf(tm1, fmaxf(s[j][2], s[j][3]));
        }
        tm0 = fmaxf(tm0, __shfl_xor_sync(0xffffffffu, tm0, 1));
        tm0 = fmaxf(tm0, __shfl_xor_sync(0xffffffffu, tm0, 2));
        tm1 = fmaxf(tm1, __shfl_xor_sync(0xffffffffu, tm1, 1));
        tm1 = fmaxf(tm1, __shfl_xor_sync(0xffffffffu, tm1, 2));

        float nm0 = fmaxf(m0, tm0), nm1 = fmaxf(m1, tm1);
        float a0 = __expf(m0 - nm0), a1 = __expf(m1 - nm1);
        float sum0 = 0.f, sum1 = 0.f;
#pragma unroll
        for (int j = 0; j < 8; j++) {
            s[j][0] = __expf(s[j][0] - nm0); sum0 += s[j][0];
            s[j][1] = __expf(s[j][1] - nm0); sum0 += s[j][1];
            s[j][2] = __expf(s[j][2] - nm1); sum1 += s[j][2];
            s[j][3] = __expf(s[j][3] - nm1); sum1 += s[j][3];
        }
        sum0 += __shfl_xor_sync(0xffffffffu, sum0, 1);
        sum0 += __shfl_xor_sync(0xffffffffu, sum0, 2);
        sum1 += __shfl_xor_sync(0xffffffffu, sum1, 1);
        sum1 += __shfl_xor_sync(0xffffffffu, sum1, 2);

        l0 = l0 * a0 + sum0; m0 = nm0;
        l1 = l1 * a1 + sum1; m1 = nm1;
#pragma unroll
        for (int j = 0; j < 8; j++) {
            o[j][0] *= a0; o[j][1] *= a0;
            o[j][2] *= a1; o[j][3] *= a1;
        }

        // ---- O += P V (P packed from S fragments; 3-term split) ----
#pragma unroll
        for (int kk = 0; kk < 4; kk++) {
            uint32_t pah[4], pal[4];
            split2(s[2 * kk][0],     s[2 * kk][1],     pah[0], pal[0]);
            split2(s[2 * kk][2],     s[2 * kk][3],     pah[1], pal[1]);
            split2(s[2 * kk + 1][0], s[2 * kk + 1][1], pah[2], pal[2]);
            split2(s[2 * kk + 1][2], s[2 * kk + 1][3], pah[3], pal[3]);
#pragma unroll
            for (int g = 0; g < 4; g++) {
                uint32_t vf[4], wf[4];
                ldsm4(vf, svh + bOff + (uint32_t)(g * 16 * FRSB) + kk * 32);
                ldsm4(wf, svl + bOff + (uint32_t)(g * 16 * FRSB) + kk * 32);
                mma16816(o[2 * g],     pah, vf[0], vf[1]);
                mma16816(o[2 * g],     pah, wf[0], wf[1]);
                mma16816(o[2 * g],     pal, vf[0], vf[1]);
                mma16816(o[2 * g + 1], pah, vf[2], vf[3]);
                mma16816(o[2 * g + 1], pah, wf[2], wf[3]);
                mma16816(o[2 * g + 1], pal, vf[2], vf[3]);
            }
        }
        __syncthreads();
    }

    // ---- epilogue: O/l as bf16 hi/lo at [b, row, h*64+d] ----
    const float il0 = 1.f / l0, il1 = 1.f / l1;
    const size_t ob0 = ((size_t)(b * SEQ) + gr0) * D_MODEL + h * HDIM + 2 * (lane & 3);
    const size_t ob1 = ob0 + (size_t)8 * D_MODEL;
#pragma unroll
    for (int j = 0; j < 8; j++) {
        uint32_t hi, lo;
        split2(o[j][0] * il0, o[j][1] * il0, hi, lo);
        *(uint32_t*)(oh + ob0 + 8 * j) = hi;
        *(uint32_t*)(ol + ob0 + 8 * j) = lo;
        split2(o[j][2] * il1, o[j][3] * il1, hi, lo);
        *(uint32_t*)(oh + ob1 + 8 * j) = hi;
        *(uint32_t*)(ol + ob1 + 8 * j) = lo;
    }
}

// ---------------------------------------------------------------------------
extern "C" void kernel_launch(void* const* d_in, const int* in_sizes, int n_in,
                              void* d_out, int out_size) {
    const float* x = (const float*)d_in[0];
    const float* W[4] = { (const float*)d_in[1], (const float*)d_in[2],
                          (const float*)d_in[3], (const float*)d_in[4] };
    float* out = (float*)d_out;

    __nv_bfloat16 *xh, *xl, *wh, *wl, *qh, *ql, *kh, *kl, *vh, *vl, *vth, *vtl, *ah, *al;
    cudaGetSymbolAddress((void**)&xh, g_xh);  cudaGetSymbolAddress((void**)&xl, g_xl);
    cudaGetSymbolAddress((void**)&wh, g_wh);  cudaGetSymbolAddress((void**)&wl, g_wl);
    cudaGetSymbolAddress((void**)&qh, g_qh);  cudaGetSymbolAddress((void**)&ql, g_ql);
    cudaGetSymbolAddress((void**)&kh, g_kh);  cudaGetSymbolAddress((void**)&kl, g_kl);
    cudaGetSymbolAddress((void**)&vh, g_vh);  cudaGetSymbolAddress((void**)&vl, g_vl);
    cudaGetSymbolAddress((void**)&vth, g_vth); cudaGetSymbolAddress((void**)&vtl, g_vtl);
    cudaGetSymbolAddress((void**)&ah, g_ah);  cudaGetSymbolAddress((void**)&al, g_al);

    const int NX4 = MTOT * D_MODEL / 4;
    const int NW4 = D_MODEL * D_MODEL / 4;

    split_bf16<<<(NX4 + 255) / 256, 256>>>((const float4*)x,
        (__nv_bfloat162*)xh, (__nv_bfloat162*)xl, NX4);
    for (int i = 0; i < 4; i++) {
        split_bf16<<<(NW4 + 255) / 256, 256>>>((const float4*)W[i],
            (__nv_bfloat162*)(wh + (size_t)i * D_MODEL * D_MODEL),
            (__nv_bfloat162*)(wl + (size_t)i * D_MODEL * D_MODEL), NW4);
    }

    cudaFuncSetAttribute(gemm_hmma, cudaFuncAttributeMaxDynamicSharedMemorySize, GSMEM);
    dim3 gridP(D_MODEL / 128, MTOT / 128);   // (8, 32)

    const size_t WS = (size_t)D_MODEL * D_MODEL;
    gemm_hmma<<<gridP, 256, GSMEM>>>(xh, xl, wh + 0 * WS, wl + 0 * WS,
                                     nullptr, qh, ql, MTOT, D_MODEL, D_MODEL);
    gemm_hmma<<<gridP, 256, GSMEM>>>(xh, xl, wh + 1 * WS, wl + 1 * WS,
                                     nullptr, kh, kl, MTOT, D_MODEL, D_MODEL);
    gemm_hmma<<<gridP, 256, GSMEM>>>(xh, xl, wh + 2 * WS, wl + 2 * WS,
                                     nullptr, vh, vl, MTOT, D_MODEL, D_MODEL);

    vtrans<<<dim3(SEQ / 64, BATCH * NHEADS), 256>>>(vh, vl, vth, vtl);

    cudaFuncSetAttribute(flash_hmma, cudaFuncAttributeMaxDynamicSharedMemorySize, FA_SMEM);
    flash_hmma<<<dim3(SEQ / 64, BATCH * NHEADS), 128, FA_SMEM>>>(
        qh, ql, kh, kl, vth, vtl, ah, al);

    gemm_hmma<<<gridP, 256, GSMEM>>>(ah, al, wh + 3 * WS, wl + 3 * WS,
                                     out, nullptr, nullptr, MTOT, D_MODEL, D_MODEL);
}